// round 6
// baseline (speedup 1.0000x reference)
#include <cuda_runtime.h>

#define NU 100000
#define NI 50000
#define NN 150000
#define HD 64
#define NE 1200000
#define SCAN_B 1024
#define NBLK ((NN + SCAN_B - 1) / SCAN_B)   // 147

typedef unsigned long long ull;

// Scratch (static device globals; zero-initialized at load)
__device__ float g_bufA[NN * HD];
__device__ float g_bufB[NN * HD];
__device__ float g_u1[NN];
__device__ float g_u2[NN];
__device__ float g_dinv[NN];
__device__ int   g_cnt[NN];          // edge in-degree (self loop NOT included)
__device__ int   g_flag[NBLK];       // scan: part+1 (0 = not ready)
__device__ int   g_off[NN + 1];
__device__ int   g_cur[NN];
__device__ int2  g_edge[NE];         // {src, norm bits}, bucketed by dst
__device__ float g_W123[HD * HD];    // W1@W2@W3
__device__ float g_bv1[HD];          // b2@W3
__device__ float g_bv2[HD];          // b1@W2@W3

#define FMA2(acc, a, b) \
    asm("fma.rn.f32x2 %0, %1, %2, %0;" : "+l"(acc) : "l"(a), "l"(b))
#define MUL2(d, a, b) \
    asm("mul.rn.f32x2 %0, %1, %2;" : "=l"(d) : "l"(a), "l"(b))
#define DUPF(d, f) \
    asm("mov.b64 %0, {%1, %1};" : "=l"(d) : "f"(f))
#define DUPR(d, r) \
    asm("mov.b64 %0, {%1, %1};" : "=l"(d) : "r"(r))

// ---------------------------------------------------------------------------
// Degree count
// ---------------------------------------------------------------------------
__global__ void k_deg(const int* __restrict__ ei) {
    int e = blockIdx.x * blockDim.x + threadIdx.x;
    if (e < NE) atomicAdd(&g_cnt[ei[NE + e]], 1);
}

// ---------------------------------------------------------------------------
// Single-pass scan of g_cnt -> g_off, g_cur; also g_dinv = rsqrt(cnt+1).
// All 147 blocks co-resident; decoupled-lookback-lite via g_flag (=total+1).
// ---------------------------------------------------------------------------
__global__ void k_scan() {
    __shared__ int ws[32];
    __shared__ int base;
    int tid = threadIdx.x;
    if (tid == 0) base = 0;
    int i = blockIdx.x * SCAN_B + tid;
    int lane = tid & 31, wid = tid >> 5;
    int cnt = (i < NN) ? g_cnt[i] : 0;
    if (i < NN) g_dinv[i] = rsqrtf((float)(cnt + 1));
    int x = cnt;
    #pragma unroll
    for (int o = 1; o < 32; o <<= 1) {
        int y = __shfl_up_sync(0xffffffffu, x, o);
        if (lane >= o) x += y;
    }
    if (lane == 31) ws[wid] = x;
    __syncthreads();
    if (wid == 0) {
        int s = ws[lane];
        #pragma unroll
        for (int o = 1; o < 32; o <<= 1) {
            int y = __shfl_up_sync(0xffffffffu, s, o);
            if (lane >= o) s += y;
        }
        ws[lane] = s;
    }
    __syncthreads();
    int incl = x + (wid > 0 ? ws[wid - 1] : 0);

    if (tid == SCAN_B - 1)
        *((volatile int*)&g_flag[blockIdx.x]) = incl + 1;

    if (tid < blockIdx.x) {
        int v;
        do { v = *((volatile int*)&g_flag[tid]); } while (v == 0);
        atomicAdd(&base, v - 1);
    }
    __syncthreads();

    if (i < NN) {
        int g = incl + base;
        g_off[i + 1] = g;
        g_cur[i] = g - cnt;
        if (i == 0) g_off[0] = 0;
    }
}

// ---------------------------------------------------------------------------
// W123 = W1@W2@W3, bv2 = b1@W2@W3, bv1 = b2@W3. One block, 256 threads.
// ---------------------------------------------------------------------------
__global__ void k_wprod(const float* __restrict__ Ws, const float* __restrict__ bs) {
    __shared__ float A[4096], B[4096], T[4096];
    int tid = threadIdx.x;
    #pragma unroll
    for (int i = 0; i < 4; i++) {
        ((float4*)A)[tid + i * 256] = ((const float4*)(Ws + 4096))[tid + i * 256]; // W2
        ((float4*)B)[tid + i * 256] = ((const float4*)(Ws + 8192))[tid + i * 256]; // W3
    }
    __syncthreads();
    #pragma unroll
    for (int i = 0; i < 16; i++) {             // T = W2@W3
        int idx = tid * 16 + i, r = idx >> 6, c = idx & 63;
        float s = 0.f;
        #pragma unroll
        for (int k = 0; k < 64; k++) s += A[r * 64 + k] * B[k * 64 + c];
        T[idx] = s;
    }
    __syncthreads();
    #pragma unroll
    for (int i = 0; i < 4; i++)
        ((float4*)A)[tid + i * 256] = ((const float4*)Ws)[tid + i * 256];          // W1
    __syncthreads();
    #pragma unroll
    for (int i = 0; i < 16; i++) {             // W123 = W1@T
        int idx = tid * 16 + i, r = idx >> 6, c = idx & 63;
        float s = 0.f;
        #pragma unroll
        for (int k = 0; k < 64; k++) s += A[r * 64 + k] * T[k * 64 + c];
        g_W123[idx] = s;
    }
    if (tid < 64) {                            // bv2 = b1@T
        float s = 0.f;
        #pragma unroll
        for (int k = 0; k < 64; k++) s += bs[k] * T[k * 64 + tid];
        g_bv2[tid] = s;
    } else if (tid < 128) {                    // bv1 = b2@W3
        int c = tid - 64;
        float s = 0.f;
        #pragma unroll
        for (int k = 0; k < 64; k++) s += bs[64 + k] * B[k * 64 + c];
        g_bv1[c] = s;
    }
}

// ---------------------------------------------------------------------------
// Bucket fill (norm from precomputed dinv)
// ---------------------------------------------------------------------------
__global__ void k_fill(const int* __restrict__ ei) {
    int e = blockIdx.x * blockDim.x + threadIdx.x;
    if (e >= NE) return;
    int s = ei[e];
    int d = ei[NE + e];
    float nrm = g_dinv[s] * g_dinv[d];
    int pos = atomicAdd(&g_cur[d], 1);
    g_edge[pos] = make_int2(s, __float_as_int(nrm));
}

// ---------------------------------------------------------------------------
// Aggregation, one WARP per node: y[i] = inv_i*x[i] + sum_e nrm_e*x[src_e]
// Each lane owns 2 cols (one f32x2 accumulator). Edge batch of 32 prefetched.
// ---------------------------------------------------------------------------
template<bool SPLIT, bool UIN, bool UOUT>
__global__ void k_agg(const float* __restrict__ xA, const float* __restrict__ xB,
                      const float* __restrict__ u_in, float* __restrict__ u_out,
                      float* __restrict__ y) {
    int node = (blockIdx.x * blockDim.x + threadIdx.x) >> 5;
    int lane = threadIdx.x & 31;
    if (node >= NN) return;

    int beg = g_off[node];
    int end = g_off[node + 1];
    float inv = 1.0f / (float)(end - beg + 1);
    ull pinv; DUPF(pinv, inv);

    const float* selfp = SPLIT ? (node < NU ? xA + (size_t)node * 64
                                            : xB + (size_t)(node - NU) * 64)
                               : xA + (size_t)node * 64;
    ull self = *(const ull*)(selfp + lane * 2);
    ull acc; MUL2(acc, self, pinv);
    float uacc = 0.0f;

    int idx = beg + lane;
    int2 ed = (idx < end) ? g_edge[idx] : make_int2(0, 0);
    for (int j0 = beg; j0 < end; j0 += 32) {
        int nidx = j0 + 32 + lane;
        int2 edn = (nidx < end) ? g_edge[nidx] : make_int2(0, 0);
        if (UOUT && (j0 + lane) < end)
            uacc += __int_as_float(ed.y) * (UIN ? u_in[ed.x] : 1.0f);
        int m = min(32, end - j0);
        #pragma unroll 4
        for (int k = 0; k < m; k++) {
            int      s  = __shfl_sync(0xffffffffu, ed.x, k);
            unsigned wb = (unsigned)__shfl_sync(0xffffffffu, ed.y, k);
            ull ww; DUPR(ww, wb);
            const float* hp = SPLIT ? (s < NU ? xA + (size_t)s * 64
                                              : xB + (size_t)(s - NU) * 64)
                                    : xA + (size_t)s * 64;
            ull h = *(const ull*)(hp + lane * 2);
            FMA2(acc, ww, h);
        }
        ed = edn;
    }

    *(ull*)(y + (size_t)node * 64 + lane * 2) = acc;

    if (UOUT) {
        #pragma unroll
        for (int o = 16; o > 0; o >>= 1)
            uacc += __shfl_down_sync(0xffffffffu, uacc, o);
        if (lane == 0)
            u_out[node] = uacc + inv * (UIN ? u_in[node] : 1.0f);
    }
}

// ---------------------------------------------------------------------------
// Final GEMM (f32x2): out[remap(n)] = y3[n]@W123 + u2*bv2 + u1*bv1 + b3
// Also copies raw embeddings to out segments 1/3 and re-zeroes g_cnt/g_flag
// for the next graph replay.
// ---------------------------------------------------------------------------
__global__ void k_gemm_final(const float* __restrict__ x, const float* __restrict__ b3,
                             const float* __restrict__ ue, const float* __restrict__ ie,
                             float* __restrict__ out) {
    __shared__ float Ws[64 * 64];
    __shared__ float Xs[32 * 68];
    int tid  = threadIdx.x;
    int row0 = blockIdx.x * 32;

    #pragma unroll
    for (int i = 0; i < 4; i++)
        ((float4*)Ws)[tid + i * 256] = ((const float4*)g_W123)[tid + i * 256];

    if (blockIdx.x == 0 && tid < NBLK) g_flag[tid] = 0;

    #pragma unroll
    for (int i = 0; i < 2; i++) {
        int idx = tid + i * 256;
        int r = idx >> 4, cc = idx & 15;
        int gr = row0 + r;
        float4 v = make_float4(0.f, 0.f, 0.f, 0.f);
        if (gr < NN) v = ((const float4*)x)[(size_t)gr * 16 + cc];
        *((float4*)&Xs[r * 68 + cc * 4]) = v;
    }
    __syncthreads();

    int r  = tid >> 3;
    int c  = tid & 7;
    int cb = c << 3;
    int gr = row0 + r;

    // embedding passthrough segments + state re-zero
    if (gr < NN) {
        if (c == 0) g_cnt[gr] = 0;
        const float4* src = (gr < NU) ? (const float4*)&ue[(size_t)gr * 64]
                                      : (const float4*)&ie[(size_t)(gr - NU) * 64];
        size_t drow = (gr < NU) ? (size_t)(NU + gr) : (size_t)(2 * NU + NI + (gr - NU));
        float4* dst = (float4*)&out[drow * 64];
        dst[2 * c]     = src[2 * c];
        dst[2 * c + 1] = src[2 * c + 1];
    }

    ull acc[4];
    {
        float un1 = (gr < NN) ? g_u1[gr] : 0.f;
        float un2 = (gr < NN) ? g_u2[gr] : 0.f;
        #pragma unroll
        for (int i = 0; i < 4; i++) {
            float lo = b3[cb + 2 * i]     + un2 * g_bv2[cb + 2 * i]     + un1 * g_bv1[cb + 2 * i];
            float hi = b3[cb + 2 * i + 1] + un2 * g_bv2[cb + 2 * i + 1] + un1 * g_bv1[cb + 2 * i + 1];
            asm("mov.b64 %0, {%1, %2};" : "=l"(acc[i]) : "f"(lo), "f"(hi));
        }
    }
    #pragma unroll
    for (int k = 0; k < 64; k++) {
        float xv = Xs[r * 68 + k];
        ull xvv; DUPF(xvv, xv);
        const ulonglong2* wp = (const ulonglong2*)&Ws[k * 64 + cb];
        ulonglong2 wa = wp[0], wb2 = wp[1];
        FMA2(acc[0], xvv, wa.x);
        FMA2(acc[1], xvv, wa.y);
        FMA2(acc[2], xvv, wb2.x);
        FMA2(acc[3], xvv, wb2.y);
    }
    if (gr < NN) {
        int orow = (gr < NU) ? gr : gr + NU;
        ulonglong2* o = (ulonglong2*)&out[(size_t)orow * 64 + cb];
        o[0] = make_ulonglong2(acc[0], acc[1]);
        o[1] = make_ulonglong2(acc[2], acc[3]);
    }
}

// ---------------------------------------------------------------------------
extern "C" void kernel_launch(void* const* d_in, const int* in_sizes, int n_in,
                              void* d_out, int out_size) {
    const int*   ei = (const int*)d_in[0];
    const float* ue = (const float*)d_in[1];
    const float* ie = (const float*)d_in[2];
    const float* Ws = (const float*)d_in[3];
    const float* bs = (const float*)d_in[4];
    float* out = (float*)d_out;

    float *bufA, *bufB, *u1, *u2;
    cudaGetSymbolAddress((void**)&bufA, g_bufA);
    cudaGetSymbolAddress((void**)&bufB, g_bufB);
    cudaGetSymbolAddress((void**)&u1,   g_u1);
    cudaGetSymbolAddress((void**)&u2,   g_u2);

    const int TB = 256;
    k_deg  <<<(NE + TB - 1) / TB, TB>>>(ei);                                      // 1
    k_scan <<<NBLK, SCAN_B>>>();                                                  // 2
    k_wprod<<<1, 256>>>(Ws, bs);                                                  // 3
    k_fill <<<(NE + TB - 1) / TB, TB>>>(ei);                                      // 4
    k_agg<true,  false, true ><<<NN * 32 / TB, TB>>>(ue, ie, nullptr, u1, bufA);  // 5 <- profiled
    k_agg<false, true,  true ><<<NN * 32 / TB, TB>>>(bufA, bufA, u1, u2, bufB);   // 6
    k_agg<false, false, false><<<NN * 32 / TB, TB>>>(bufB, bufB, nullptr, nullptr, bufA); // 7
    k_gemm_final<<<(NN + 31) / 32, TB>>>(bufA, bs + 2 * 64, ue, ie, out);         // 8
}

// round 8
// speedup vs baseline: 1.1294x; 1.1294x over previous
#include <cuda_runtime.h>

#define NU 100000
#define NI 50000
#define NN 150000
#define HD 64
#define NE 1200000
#define SCAN_B 1024
#define NBLK ((NN + SCAN_B - 1) / SCAN_B)   // 147

typedef unsigned long long ull;

// Scratch (static device globals; zero-initialized at load)
__device__ float g_bufA[NN * HD];
__device__ float g_bufB[NN * HD];
__device__ float g_u1[NN];
__device__ float g_u2[NN];
__device__ float g_dinv[NN];
__device__ int   g_cnt[NN];          // edge in-degree (self loop NOT included)
__device__ int   g_flag[NBLK];       // scan: total+1 (0 = not ready)
__device__ int   g_off[NN + 1];
__device__ int   g_cur[NN];
__device__ int2  g_edge[NE];         // {src, norm bits}, bucketed by dst
__device__ float g_W123[HD * HD];    // W1@W2@W3
__device__ float g_bv1[HD];          // b2@W3
__device__ float g_bv2[HD];          // b1@W2@W3

#define FMA2(acc, a, b) \
    asm("fma.rn.f32x2 %0, %1, %2, %0;" : "+l"(acc) : "l"(a), "l"(b))
#define MUL2(d, a, b) \
    asm("mul.rn.f32x2 %0, %1, %2;" : "=l"(d) : "l"(a), "l"(b))
#define DUPF(d, f) \
    asm("mov.b64 %0, {%1, %1};" : "=l"(d) : "f"(f))
#define DUPR(d, r) \
    asm("mov.b64 %0, {%1, %1};" : "=l"(d) : "r"(r))

// ---------------------------------------------------------------------------
// Degree count
// ---------------------------------------------------------------------------
__global__ void k_deg(const int* __restrict__ ei) {
    int e = blockIdx.x * blockDim.x + threadIdx.x;
    if (e < NE) atomicAdd(&g_cnt[ei[NE + e]], 1);
}

// ---------------------------------------------------------------------------
// Fused: blocks 0..NBLK-1 = single-pass scan of g_cnt (all co-resident,
// decoupled-lookback-lite via g_flag) + dinv; block NBLK = weight products.
// ---------------------------------------------------------------------------
__global__ void __launch_bounds__(1024)
k_scan_wprod(const float* __restrict__ Wsrc, const float* __restrict__ bs) {
    __shared__ float smem[3 * 4096 + 64];
    int tid = threadIdx.x;

    if (blockIdx.x < NBLK) {
        // ---- scan part ----
        int* ws    = (int*)smem;
        int* basep = (int*)smem + 40;
        if (tid == 0) *basep = 0;
        int i = blockIdx.x * SCAN_B + tid;
        int lane = tid & 31, wid = tid >> 5;
        int cnt = (i < NN) ? g_cnt[i] : 0;
        if (i < NN) g_dinv[i] = rsqrtf((float)(cnt + 1));
        int x = cnt;
        #pragma unroll
        for (int o = 1; o < 32; o <<= 1) {
            int y = __shfl_up_sync(0xffffffffu, x, o);
            if (lane >= o) x += y;
        }
        if (lane == 31) ws[wid] = x;
        __syncthreads();
        if (wid == 0) {
            int s = ws[lane];
            #pragma unroll
            for (int o = 1; o < 32; o <<= 1) {
                int y = __shfl_up_sync(0xffffffffu, s, o);
                if (lane >= o) s += y;
            }
            ws[lane] = s;
        }
        __syncthreads();
        int incl = x + (wid > 0 ? ws[wid - 1] : 0);

        if (tid == SCAN_B - 1)
            *((volatile int*)&g_flag[blockIdx.x]) = incl + 1;

        if (tid < blockIdx.x) {
            int v;
            do { v = *((volatile int*)&g_flag[tid]); } while (v == 0);
            atomicAdd(basep, v - 1);
        }
        __syncthreads();

        if (i < NN) {
            int g = incl + *basep;
            g_off[i + 1] = g;
            g_cur[i] = g - cnt;
            if (i == 0) g_off[0] = 0;
        }
    } else {
        // ---- wprod part: W123 = W1@W2@W3, bv2 = b1@W2@W3, bv1 = b2@W3 ----
        float* A = smem;
        float* B = smem + 4096;
        float* T = smem + 8192;
        ((float4*)A)[tid] = ((const float4*)(Wsrc + 4096))[tid];   // W2
        ((float4*)B)[tid] = ((const float4*)(Wsrc + 8192))[tid];   // W3
        __syncthreads();
        #pragma unroll
        for (int i = 0; i < 4; i++) {            // T = W2@W3
            int idx = tid * 4 + i, r = idx >> 6, c = idx & 63;
            float s = 0.f;
            #pragma unroll
            for (int k = 0; k < 64; k++) s += A[r * 64 + k] * B[k * 64 + c];
            T[idx] = s;
        }
        __syncthreads();
        ((float4*)A)[tid] = ((const float4*)Wsrc)[tid];            // W1
        __syncthreads();
        #pragma unroll
        for (int i = 0; i < 4; i++) {            // W123 = W1@T
            int idx = tid * 4 + i, r = idx >> 6, c = idx & 63;
            float s = 0.f;
            #pragma unroll
            for (int k = 0; k < 64; k++) s += A[r * 64 + k] * T[k * 64 + c];
            g_W123[idx] = s;
        }
        if (tid < 64) {                          // bv2 = b1@T
            float s = 0.f;
            #pragma unroll
            for (int k = 0; k < 64; k++) s += bs[k] * T[k * 64 + tid];
            g_bv2[tid] = s;
        } else if (tid < 128) {                  // bv1 = b2@W3
            int c = tid - 64;
            float s = 0.f;
            #pragma unroll
            for (int k = 0; k < 64; k++) s += bs[64 + k] * B[k * 64 + c];
            g_bv1[c] = s;
        }
    }
}

// ---------------------------------------------------------------------------
// Bucket fill (norm from precomputed dinv)
// ---------------------------------------------------------------------------
__global__ void k_fill(const int* __restrict__ ei) {
    int e = blockIdx.x * blockDim.x + threadIdx.x;
    if (e >= NE) return;
    int s = ei[e];
    int d = ei[NE + e];
    float nrm = g_dinv[s] * g_dinv[d];
    int pos = atomicAdd(&g_cur[d], 1);
    g_edge[pos] = make_int2(s, __float_as_int(nrm));
}

// ---------------------------------------------------------------------------
// Aggregation: y[i] = inv_i * x[i] + sum_e nrm_e * x[src_e]
// 8 threads/node (4 nodes/warp). Inner batch of 8 edges fully unrolled;
// padded slots carry w=0 (exact no-op). Next batch prefetched.
// ---------------------------------------------------------------------------
template<bool SPLIT, bool UIN, bool UOUT>
__global__ void k_agg(const float* __restrict__ xA, const float* __restrict__ xB,
                      const float* __restrict__ u_in, float* __restrict__ u_out,
                      float* __restrict__ y) {
    int t = blockIdx.x * blockDim.x + threadIdx.x;
    int node = t >> 3;
    int c = t & 7;
    if (node >= NN) return;
    unsigned gmask = 0xFFu << (threadIdx.x & 24);

    int beg = g_off[node];
    int end = g_off[node + 1];
    float inv = 1.0f / (float)(end - beg + 1);
    ull pinv; DUPF(pinv, inv);

    const float* selfp = SPLIT ? (node < NU ? xA + (size_t)node * 64
                                            : xB + (size_t)(node - NU) * 64)
                               : xA + (size_t)node * 64;
    ulonglong2 s0 = *(const ulonglong2*)(selfp + c * 8);
    ulonglong2 s1 = *(const ulonglong2*)(selfp + c * 8 + 4);
    ull acc0, acc1, acc2, acc3;
    MUL2(acc0, s0.x, pinv); MUL2(acc1, s0.y, pinv);
    MUL2(acc2, s1.x, pinv); MUL2(acc3, s1.y, pinv);
    float uacc = 0.0f;

    int idx = beg + c;
    int2 ed = (idx < end) ? g_edge[idx] : make_int2(0, 0);
    for (int j0 = beg; j0 < end; j0 += 8) {
        int nidx = j0 + 8 + c;
        int2 edn = (nidx < end) ? g_edge[nidx] : make_int2(0, 0);
        if (UOUT && (j0 + c) < end)
            uacc += __int_as_float(ed.y) * (UIN ? u_in[ed.x] : 1.0f);
        #pragma unroll
        for (int k = 0; k < 8; k++) {
            int      s  = __shfl_sync(gmask, ed.x, k, 8);
            unsigned wb = (unsigned)__shfl_sync(gmask, ed.y, k, 8);
            ull ww; DUPR(ww, wb);
            const float* hp = SPLIT ? (s < NU ? xA + (size_t)s * 64
                                              : xB + (size_t)(s - NU) * 64)
                                    : xA + (size_t)s * 64;
            ulonglong2 h0 = *(const ulonglong2*)(hp + c * 8);
            ulonglong2 h1 = *(const ulonglong2*)(hp + c * 8 + 4);
            FMA2(acc0, ww, h0.x); FMA2(acc1, ww, h0.y);
            FMA2(acc2, ww, h1.x); FMA2(acc3, ww, h1.y);
        }
        ed = edn;
    }

    ulonglong2* yo = (ulonglong2*)(y + (size_t)node * 64 + c * 8);
    yo[0] = make_ulonglong2(acc0, acc1);
    yo[1] = make_ulonglong2(acc2, acc3);

    if (UOUT) {
        #pragma unroll
        for (int o = 4; o > 0; o >>= 1)
            uacc += __shfl_down_sync(gmask, uacc, o, 8);
        if (c == 0) u_out[node] = uacc + inv * (UIN ? u_in[node] : 1.0f);
    }
}

// ---------------------------------------------------------------------------
// Final GEMM (f32x2): out[remap(n)] = y3[n]@W123 + u2*bv2 + u1*bv1 + b3
// Also copies raw embeddings to out segments 1/3 and re-zeroes g_cnt/g_flag
// for the next graph replay.
// ---------------------------------------------------------------------------
__global__ void k_gemm_final(const float* __restrict__ x, const float* __restrict__ b3,
                             const float* __restrict__ ue, const float* __restrict__ ie,
                             float* __restrict__ out) {
    __shared__ float Ws[64 * 64];
    __shared__ float Xs[32 * 68];
    int tid  = threadIdx.x;
    int row0 = blockIdx.x * 32;

    #pragma unroll
    for (int i = 0; i < 4; i++)
        ((float4*)Ws)[tid + i * 256] = ((const float4*)g_W123)[tid + i * 256];

    if (blockIdx.x == 0 && tid < NBLK) g_flag[tid] = 0;

    #pragma unroll
    for (int i = 0; i < 2; i++) {
        int idx = tid + i * 256;
        int r = idx >> 4, cc = idx & 15;
        int gr = row0 + r;
        float4 v = make_float4(0.f, 0.f, 0.f, 0.f);
        if (gr < NN) v = ((const float4*)x)[(size_t)gr * 16 + cc];
        *((float4*)&Xs[r * 68 + cc * 4]) = v;
    }
    __syncthreads();

    int r  = tid >> 3;
    int c  = tid & 7;
    int cb = c << 3;
    int gr = row0 + r;

    // embedding passthrough segments + state re-zero
    if (gr < NN) {
        if (c == 0) g_cnt[gr] = 0;
        const float4* src = (gr < NU) ? (const float4*)&ue[(size_t)gr * 64]
                                      : (const float4*)&ie[(size_t)(gr - NU) * 64];
        size_t drow = (gr < NU) ? (size_t)(NU + gr) : (size_t)(2 * NU + NI + (gr - NU));
        float4* dst = (float4*)&out[drow * 64];
        dst[2 * c]     = src[2 * c];
        dst[2 * c + 1] = src[2 * c + 1];
    }

    ull acc[4];
    {
        float un1 = (gr < NN) ? g_u1[gr] : 0.f;
        float un2 = (gr < NN) ? g_u2[gr] : 0.f;
        #pragma unroll
        for (int i = 0; i < 4; i++) {
            float lo = b3[cb + 2 * i]     + un2 * g_bv2[cb + 2 * i]     + un1 * g_bv1[cb + 2 * i];
            float hi = b3[cb + 2 * i + 1] + un2 * g_bv2[cb + 2 * i + 1] + un1 * g_bv1[cb + 2 * i + 1];
            asm("mov.b64 %0, {%1, %2};" : "=l"(acc[i]) : "f"(lo), "f"(hi));
        }
    }
    #pragma unroll
    for (int k = 0; k < 64; k++) {
        float xv = Xs[r * 68 + k];
        ull xvv; DUPF(xvv, xv);
        const ulonglong2* wp = (const ulonglong2*)&Ws[k * 64 + cb];
        ulonglong2 wa = wp[0], wb2 = wp[1];
        FMA2(acc[0], xvv, wa.x);
        FMA2(acc[1], xvv, wa.y);
        FMA2(acc[2], xvv, wb2.x);
        FMA2(acc[3], xvv, wb2.y);
    }
    if (gr < NN) {
        int orow = (gr < NU) ? gr : gr + NU;
        ulonglong2* o = (ulonglong2*)&out[(size_t)orow * 64 + cb];
        o[0] = make_ulonglong2(acc[0], acc[1]);
        o[1] = make_ulonglong2(acc[2], acc[3]);
    }
}

// ---------------------------------------------------------------------------
extern "C" void kernel_launch(void* const* d_in, const int* in_sizes, int n_in,
                              void* d_out, int out_size) {
    const int*   ei = (const int*)d_in[0];
    const float* ue = (const float*)d_in[1];
    const float* ie = (const float*)d_in[2];
    const float* Ws = (const float*)d_in[3];
    const float* bs = (const float*)d_in[4];
    float* out = (float*)d_out;

    float *bufA, *bufB, *u1, *u2;
    cudaGetSymbolAddress((void**)&bufA, g_bufA);
    cudaGetSymbolAddress((void**)&bufB, g_bufB);
    cudaGetSymbolAddress((void**)&u1,   g_u1);
    cudaGetSymbolAddress((void**)&u2,   g_u2);

    const int TB = 256;
    const int AGG_GRID = (NN * 8 + TB - 1) / TB;   // ceil! (4688)
    k_deg       <<<(NE + TB - 1) / TB, TB>>>(ei);                                   // 1
    k_scan_wprod<<<NBLK + 1, SCAN_B>>>(Ws, bs);                                     // 2
    k_fill      <<<(NE + TB - 1) / TB, TB>>>(ei);                                   // 3
    k_agg<true,  false, true ><<<AGG_GRID, TB>>>(ue, ie, nullptr, u1, bufA);        // 4 <- profiled
    k_agg<false, true,  true ><<<AGG_GRID, TB>>>(bufA, bufA, u1, u2, bufB);         // 5
    k_agg<false, false, false><<<AGG_GRID, TB>>>(bufB, bufB, nullptr, nullptr, bufA); // 6
    k_gemm_final<<<(NN + 31) / 32, TB>>>(bufA, bs + 2 * 64, ue, ie, out);           // 7
}

// round 9
// speedup vs baseline: 1.1953x; 1.0584x over previous
#include <cuda_runtime.h>

#define NU 100000
#define NI 50000
#define NN 150000
#define HD 64
#define NE 1200000
#define SCAN_B 1024
#define NBLK ((NN + SCAN_B - 1) / SCAN_B)   // 147

typedef unsigned long long ull;

// Scratch (static device globals; zero-initialized at load)
__device__ float g_bufA[NN * HD];
__device__ float g_bufB[NN * HD];
__device__ float g_u1[NN];
__device__ float g_u2[NN];
__device__ float g_dinv[NN];
__device__ int   g_cnt[NN];          // edge in-degree (self loop NOT included)
__device__ int   g_flag[NBLK];       // scan: total+1 (0 = not ready)
__device__ int   g_off[NN + 1];
__device__ int   g_cur[NN];
__device__ int2  g_edge[NE];         // {src, norm bits}, bucketed by dst
__device__ float g_W123[HD * HD];    // W1@W2@W3
__device__ float g_bv1[HD];          // b2@W3
__device__ float g_bv2[HD];          // b1@W2@W3

#define FMA2(acc, a, b) \
    asm("fma.rn.f32x2 %0, %1, %2, %0;" : "+l"(acc) : "l"(a), "l"(b))
#define MUL2(d, a, b) \
    asm("mul.rn.f32x2 %0, %1, %2;" : "=l"(d) : "l"(a), "l"(b))
#define DUPF(d, f) \
    asm("mov.b64 %0, {%1, %1};" : "=l"(d) : "f"(f))
#define DUPR(d, r) \
    asm("mov.b64 %0, {%1, %1};" : "=l"(d) : "r"(r))

// ---------------------------------------------------------------------------
// Degree count
// ---------------------------------------------------------------------------
__global__ void k_deg(const int* __restrict__ ei) {
    int e = blockIdx.x * blockDim.x + threadIdx.x;
    if (e < NE) atomicAdd(&g_cnt[ei[NE + e]], 1);
}

// ---------------------------------------------------------------------------
// Fused: blocks 0..NBLK-1 = single-pass scan of g_cnt (all co-resident,
// decoupled-lookback-lite via g_flag) + dinv; block NBLK = weight products.
// ---------------------------------------------------------------------------
__global__ void __launch_bounds__(1024)
k_scan_wprod(const float* __restrict__ Wsrc, const float* __restrict__ bs) {
    __shared__ float smem[3 * 4096 + 64];
    int tid = threadIdx.x;

    if (blockIdx.x < NBLK) {
        // ---- scan part ----
        int* ws    = (int*)smem;
        int* basep = (int*)smem + 40;
        if (tid == 0) *basep = 0;
        int i = blockIdx.x * SCAN_B + tid;
        int lane = tid & 31, wid = tid >> 5;
        int cnt = (i < NN) ? g_cnt[i] : 0;
        if (i < NN) g_dinv[i] = rsqrtf((float)(cnt + 1));
        int x = cnt;
        #pragma unroll
        for (int o = 1; o < 32; o <<= 1) {
            int y = __shfl_up_sync(0xffffffffu, x, o);
            if (lane >= o) x += y;
        }
        if (lane == 31) ws[wid] = x;
        __syncthreads();
        if (wid == 0) {
            int s = ws[lane];
            #pragma unroll
            for (int o = 1; o < 32; o <<= 1) {
                int y = __shfl_up_sync(0xffffffffu, s, o);
                if (lane >= o) s += y;
            }
            ws[lane] = s;
        }
        __syncthreads();
        int incl = x + (wid > 0 ? ws[wid - 1] : 0);

        if (tid == SCAN_B - 1)
            *((volatile int*)&g_flag[blockIdx.x]) = incl + 1;

        if (tid < blockIdx.x) {
            int v;
            do { v = *((volatile int*)&g_flag[tid]); } while (v == 0);
            atomicAdd(basep, v - 1);
        }
        __syncthreads();

        if (i < NN) {
            int g = incl + *basep;
            g_off[i + 1] = g;
            g_cur[i] = g - cnt;
            if (i == 0) g_off[0] = 0;
        }
    } else {
        // ---- wprod part: W123 = W1@W2@W3, bv2 = b1@W2@W3, bv1 = b2@W3 ----
        float* A = smem;
        float* B = smem + 4096;
        float* T = smem + 8192;
        ((float4*)A)[tid] = ((const float4*)(Wsrc + 4096))[tid];   // W2
        ((float4*)B)[tid] = ((const float4*)(Wsrc + 8192))[tid];   // W3
        __syncthreads();
        #pragma unroll
        for (int i = 0; i < 4; i++) {            // T = W2@W3
            int idx = tid * 4 + i, r = idx >> 6, c = idx & 63;
            float s = 0.f;
            #pragma unroll
            for (int k = 0; k < 64; k++) s += A[r * 64 + k] * B[k * 64 + c];
            T[idx] = s;
        }
        __syncthreads();
        ((float4*)A)[tid] = ((const float4*)Wsrc)[tid];            // W1
        __syncthreads();
        #pragma unroll
        for (int i = 0; i < 4; i++) {            // W123 = W1@T
            int idx = tid * 4 + i, r = idx >> 6, c = idx & 63;
            float s = 0.f;
            #pragma unroll
            for (int k = 0; k < 64; k++) s += A[r * 64 + k] * T[k * 64 + c];
            g_W123[idx] = s;
        }
        if (tid < 64) {                          // bv2 = b1@T
            float s = 0.f;
            #pragma unroll
            for (int k = 0; k < 64; k++) s += bs[k] * T[k * 64 + tid];
            g_bv2[tid] = s;
        } else if (tid < 128) {                  // bv1 = b2@W3
            int c = tid - 64;
            float s = 0.f;
            #pragma unroll
            for (int k = 0; k < 64; k++) s += bs[64 + k] * B[k * 64 + c];
            g_bv1[c] = s;
        }
    }
}

// ---------------------------------------------------------------------------
// Bucket fill (norm from precomputed dinv)
// ---------------------------------------------------------------------------
__global__ void k_fill(const int* __restrict__ ei) {
    int e = blockIdx.x * blockDim.x + threadIdx.x;
    if (e >= NE) return;
    int s = ei[e];
    int d = ei[NE + e];
    float nrm = g_dinv[s] * g_dinv[d];
    int pos = atomicAdd(&g_cur[d], 1);
    g_edge[pos] = make_int2(s, __float_as_int(nrm));
}

// ---------------------------------------------------------------------------
// Aggregation: y[i] = inv_i * x[i] + sum_e nrm_e * x[src_e]
// 8 threads/node (4 nodes/warp). Lane c owns cols [4c,4c+4) and [32+4c,+4):
// each warp-wide LDG.128 covers one contiguous 128B line per group (full
// sectors). Inner batch of 8 edges fully unrolled; pad slots carry w=0.
// ---------------------------------------------------------------------------
template<bool SPLIT, bool UIN, bool UOUT>
__global__ void k_agg(const float* __restrict__ xA, const float* __restrict__ xB,
                      const float* __restrict__ u_in, float* __restrict__ u_out,
                      float* __restrict__ y) {
    int t = blockIdx.x * blockDim.x + threadIdx.x;
    int node = t >> 3;
    int c = t & 7;
    if (node >= NN) return;
    unsigned gmask = 0xFFu << (threadIdx.x & 24);

    int beg = g_off[node];
    int end = g_off[node + 1];
    float inv = 1.0f / (float)(end - beg + 1);
    ull pinv; DUPF(pinv, inv);

    const float* selfp = SPLIT ? (node < NU ? xA + (size_t)node * 64
                                            : xB + (size_t)(node - NU) * 64)
                               : xA + (size_t)node * 64;
    ulonglong2 s0 = *(const ulonglong2*)(selfp + c * 4);        // line 0: bytes 16c
    ulonglong2 s1 = *(const ulonglong2*)(selfp + 32 + c * 4);   // line 1
    ull acc0, acc1, acc2, acc3;
    MUL2(acc0, s0.x, pinv); MUL2(acc1, s0.y, pinv);
    MUL2(acc2, s1.x, pinv); MUL2(acc3, s1.y, pinv);
    float uacc = 0.0f;

    int idx = beg + c;
    int2 ed = (idx < end) ? g_edge[idx] : make_int2(0, 0);
    for (int j0 = beg; j0 < end; j0 += 8) {
        int nidx = j0 + 8 + c;
        int2 edn = (nidx < end) ? g_edge[nidx] : make_int2(0, 0);
        if (UOUT && (j0 + c) < end)
            uacc += __int_as_float(ed.y) * (UIN ? u_in[ed.x] : 1.0f);
        #pragma unroll
        for (int k = 0; k < 8; k++) {
            int      s  = __shfl_sync(gmask, ed.x, k, 8);
            unsigned wb = (unsigned)__shfl_sync(gmask, ed.y, k, 8);
            ull ww; DUPR(ww, wb);
            const float* hp = SPLIT ? (s < NU ? xA + (size_t)s * 64
                                              : xB + (size_t)(s - NU) * 64)
                                    : xA + (size_t)s * 64;
            ulonglong2 h0 = *(const ulonglong2*)(hp + c * 4);
            ulonglong2 h1 = *(const ulonglong2*)(hp + 32 + c * 4);
            FMA2(acc0, ww, h0.x); FMA2(acc1, ww, h0.y);
            FMA2(acc2, ww, h1.x); FMA2(acc3, ww, h1.y);
        }
        ed = edn;
    }

    *(ulonglong2*)(y + (size_t)node * 64 + c * 4)      = make_ulonglong2(acc0, acc1);
    *(ulonglong2*)(y + (size_t)node * 64 + 32 + c * 4) = make_ulonglong2(acc2, acc3);

    if (UOUT) {
        #pragma unroll
        for (int o = 4; o > 0; o >>= 1)
            uacc += __shfl_down_sync(gmask, uacc, o, 8);
        if (c == 0) u_out[node] = uacc + inv * (UIN ? u_in[node] : 1.0f);
    }
}

// ---------------------------------------------------------------------------
// Final GEMM (f32x2): out[remap(n)] = y3[n]@W123 + u2*bv2 + u1*bv1 + b3
// Also copies raw embeddings to out segments 1/3 and re-zeroes g_cnt/g_flag
// for the next graph replay.
// ---------------------------------------------------------------------------
__global__ void k_gemm_final(const float* __restrict__ x, const float* __restrict__ b3,
                             const float* __restrict__ ue, const float* __restrict__ ie,
                             float* __restrict__ out) {
    __shared__ float Ws[64 * 64];
    __shared__ float Xs[32 * 68];
    int tid  = threadIdx.x;
    int row0 = blockIdx.x * 32;

    #pragma unroll
    for (int i = 0; i < 4; i++)
        ((float4*)Ws)[tid + i * 256] = ((const float4*)g_W123)[tid + i * 256];

    if (blockIdx.x == 0 && tid < NBLK) g_flag[tid] = 0;

    #pragma unroll
    for (int i = 0; i < 2; i++) {
        int idx = tid + i * 256;
        int r = idx >> 4, cc = idx & 15;
        int gr = row0 + r;
        float4 v = make_float4(0.f, 0.f, 0.f, 0.f);
        if (gr < NN) v = ((const float4*)x)[(size_t)gr * 16 + cc];
        *((float4*)&Xs[r * 68 + cc * 4]) = v;
    }
    __syncthreads();

    int r  = tid >> 3;
    int c  = tid & 7;
    int cb = c << 3;
    int gr = row0 + r;

    // embedding passthrough segments + state re-zero
    if (gr < NN) {
        if (c == 0) g_cnt[gr] = 0;
        const float4* src = (gr < NU) ? (const float4*)&ue[(size_t)gr * 64]
                                      : (const float4*)&ie[(size_t)(gr - NU) * 64];
        size_t drow = (gr < NU) ? (size_t)(NU + gr) : (size_t)(2 * NU + NI + (gr - NU));
        float4* dst = (float4*)&out[drow * 64];
        dst[2 * c]     = src[2 * c];
        dst[2 * c + 1] = src[2 * c + 1];
    }

    ull acc[4];
    {
        float un1 = (gr < NN) ? g_u1[gr] : 0.f;
        float un2 = (gr < NN) ? g_u2[gr] : 0.f;
        #pragma unroll
        for (int i = 0; i < 4; i++) {
            float lo = b3[cb + 2 * i]     + un2 * g_bv2[cb + 2 * i]     + un1 * g_bv1[cb + 2 * i];
            float hi = b3[cb + 2 * i + 1] + un2 * g_bv2[cb + 2 * i + 1] + un1 * g_bv1[cb + 2 * i + 1];
            asm("mov.b64 %0, {%1, %2};" : "=l"(acc[i]) : "f"(lo), "f"(hi));
        }
    }
    #pragma unroll
    for (int k = 0; k < 64; k++) {
        float xv = Xs[r * 68 + k];
        ull xvv; DUPF(xvv, xv);
        const ulonglong2* wp = (const ulonglong2*)&Ws[k * 64 + cb];
        ulonglong2 wa = wp[0], wb2 = wp[1];
        FMA2(acc[0], xvv, wa.x);
        FMA2(acc[1], xvv, wa.y);
        FMA2(acc[2], xvv, wb2.x);
        FMA2(acc[3], xvv, wb2.y);
    }
    if (gr < NN) {
        int orow = (gr < NU) ? gr : gr + NU;
        ulonglong2* o = (ulonglong2*)&out[(size_t)orow * 64 + cb];
        o[0] = make_ulonglong2(acc[0], acc[1]);
        o[1] = make_ulonglong2(acc[2], acc[3]);
    }
}

// ---------------------------------------------------------------------------
extern "C" void kernel_launch(void* const* d_in, const int* in_sizes, int n_in,
                              void* d_out, int out_size) {
    const int*   ei = (const int*)d_in[0];
    const float* ue = (const float*)d_in[1];
    const float* ie = (const float*)d_in[2];
    const float* Ws = (const float*)d_in[3];
    const float* bs = (const float*)d_in[4];
    float* out = (float*)d_out;

    float *bufA, *bufB, *u1, *u2;
    cudaGetSymbolAddress((void**)&bufA, g_bufA);
    cudaGetSymbolAddress((void**)&bufB, g_bufB);
    cudaGetSymbolAddress((void**)&u1,   g_u1);
    cudaGetSymbolAddress((void**)&u2,   g_u2);

    const int TB = 256;
    const int AGG_GRID = (NN * 8 + TB - 1) / TB;   // ceil (4688)
    k_deg       <<<(NE + TB - 1) / TB, TB>>>(ei);                                   // 1
    k_scan_wprod<<<NBLK + 1, SCAN_B>>>(Ws, bs);                                     // 2
    k_fill      <<<(NE + TB - 1) / TB, TB>>>(ei);                                   // 3
    k_agg<true,  false, true ><<<AGG_GRID, TB>>>(ue, ie, nullptr, u1, bufA);        // 4 <- profiled
    k_agg<false, true,  true ><<<AGG_GRID, TB>>>(bufA, bufA, u1, u2, bufB);         // 5
    k_agg<false, false, false><<<AGG_GRID, TB>>>(bufB, bufB, nullptr, nullptr, bufA); // 6
    k_gemm_final<<<(NN + 31) / 32, TB>>>(bufA, bs + 2 * 64, ue, ie, out);           // 7
}